// round 10
// baseline (speedup 1.0000x reference)
#include <cuda_runtime.h>
#include <cuda_fp16.h>
#include <cstdint>

// GraphAttentionLayer B=8,T=2048,D=256.
// Key identity: w(i,j)=exp(lrelu(s1_i+s2_j)) separates:
//   e>0: up_i*ep_j  (up=exp(s1), ep=exp(s2));  e<=0: un_i*en_j (0.2-scaled).
// Positive set is a prefix of j sorted by s2 desc => attention GEMM becomes
// prefix(P)/suffix(N) sums + per-row binary search. O(T^2 D) -> O(T D).
//  k1: h = x@W^T (split-3 fp16 mma), s1/s2, h stored fp32
//  k_sort: per-batch bitonic sort of s2 + scalar prefix/suffix scans (dp/dn)
//  k_scanloc: per-segment vector scans of ep*h (prefix) / en*h (suffix)
//  k_segscan: scan of segment totals (+boundary rows)
//  k_out: per-row k_i via binary search; combine, normalize, ELU

#define B_ 8
#define T_ 2048
#define NEG_SLOPE 0.2f

__device__ float g_hf[B_ * T_ * 256];      // 16 MB fp32 h
__device__ float g_s1[B_ * T_];
__device__ float g_s2[B_ * T_];
__device__ float g_s2s[B_ * T_];           // sorted s2 (desc)
__device__ int   g_perm[B_ * T_];          // sort permutation
__device__ float g_ep[B_ * T_];            // exp(s2) in sorted order
__device__ float g_en[B_ * T_];            // exp(.2*s2) in sorted order
__device__ float g_dp[B_ * 2049];          // scalar prefix of ep
__device__ float g_dn[B_ * 2049];          // scalar suffix of en
__device__ float g_Pl[B_ * 2049 * 256];    // local (per-seg) prefix of ep*h
__device__ float g_Nl[B_ * 2049 * 256];    // local (per-seg) suffix of en*h
__device__ float g_segP[B_ * 16 * 256];
__device__ float g_segN[B_ * 16 * 256];
__device__ float g_offP[B_ * 17 * 256];
__device__ float g_offN[B_ * 17 * 256];

// ---------------- helpers ----------------------------------------------------
__device__ __forceinline__ uint32_t smem_u32(const void* p) {
  uint32_t a;
  asm("{ .reg .u64 t; cvta.to.shared.u64 t, %1; cvt.u32.u64 %0, t; }"
      : "=r"(a) : "l"(p));
  return a;
}
__device__ __forceinline__ void ldsm4(uint32_t addr, uint32_t r[4]) {
  asm volatile("ldmatrix.sync.aligned.m8n8.x4.shared.b16 {%0,%1,%2,%3}, [%4];"
               : "=r"(r[0]), "=r"(r[1]), "=r"(r[2]), "=r"(r[3]) : "r"(addr));
}
__device__ __forceinline__ void mma16816(float c[4], const uint32_t a[4],
                                         uint32_t b0, uint32_t b1) {
  asm volatile(
      "mma.sync.aligned.m16n8k16.row.col.f32.f16.f16.f32 "
      "{%0,%1,%2,%3}, {%4,%5,%6,%7}, {%8,%9}, {%0,%1,%2,%3};"
      : "+f"(c[0]), "+f"(c[1]), "+f"(c[2]), "+f"(c[3])
      : "r"(a[0]), "r"(a[1]), "r"(a[2]), "r"(a[3]), "r"(b0), "r"(b1));
}
__device__ __forceinline__ void cpa16(uint32_t dst, const void* src) {
  asm volatile("cp.async.cg.shared.global [%0], [%1], 16;" :: "r"(dst), "l"(src)
               : "memory");
}
#define CP_COMMIT() asm volatile("cp.async.commit_group;" ::: "memory")
#define CP_WAIT(n) asm volatile("cp.async.wait_group %0;" :: "n"(n) : "memory")

__device__ __forceinline__ void split8(const float* v, uint4& hi, uint4& lo) {
  uint32_t h[4], l[4];
#pragma unroll
  for (int q = 0; q < 4; q++) {
    float a = v[2 * q], b = v[2 * q + 1];
    __half ah = __float2half_rn(a), bh = __float2half_rn(b);
    __half2 hv; hv.x = ah; hv.y = bh; h[q] = *(uint32_t*)&hv;
    __half2 lv;
    lv.x = __float2half_rn(a - __half2float(ah));
    lv.y = __float2half_rn(b - __half2float(bh));
    l[q] = *(uint32_t*)&lv;
  }
  hi = make_uint4(h[0], h[1], h[2], h[3]);
  lo = make_uint4(l[0], l[1], l[2], l[3]);
}

// ============================================================================
// K1: h = x @ W^T (split-3 fp16 mma), epilogue: s1/s2 + h fp32 store.
// ============================================================================
#define K1_FX 0
#define K1_FW 34816
#define K1_AH 104448
#define K1_AL 122880
#define K1_BH 141312
#define K1_BL 178176
#define K1_AS 215040
#define K1_R1 217088
#define K1_R2 219136
#define K1_SMEM 221184

__global__ __launch_bounds__(512, 1) void k1(
    const float* __restrict__ x, const float* __restrict__ W,
    const float* __restrict__ a) {
  extern __shared__ char sm[];
  const uint32_t SB = smem_u32(sm);
  const int t = threadIdx.x, lane = t & 31, wid = t >> 5;
  const int warpM = wid >> 2, warpN = wid & 3;
  const int i0 = blockIdx.x * 128;

#define K1_LOADF32(cc) do {                                                   \
    const int k0_ = (cc) * 64;                                                \
    _Pragma("unroll")                                                         \
    for (int v = 0; v < 4; v++) {                                             \
      int u = v * 512 + t, row = u >> 4, seg = u & 15;                        \
      cpa16(SB + K1_FX + (uint32_t)(row * 68 + seg * 4) * 4,                  \
            &x[(size_t)(i0 + row) * 256 + k0_ + seg * 4]);                    \
    }                                                                         \
    _Pragma("unroll")                                                         \
    for (int v = 0; v < 8; v++) {                                             \
      int u = v * 512 + t, row = u >> 4, seg = u & 15;                        \
      cpa16(SB + K1_FW + (uint32_t)(row * 68 + seg * 4) * 4,                  \
            &W[(size_t)row * 256 + k0_ + seg * 4]);                           \
    }                                                                         \
  } while (0)

  K1_LOADF32(0);
  CP_COMMIT();
  ((float*)(sm + K1_AS))[t] = a[t];

  float c[2][8][4];
#pragma unroll
  for (int r = 0; r < 2; r++)
#pragma unroll
    for (int f = 0; f < 8; f++)
#pragma unroll
      for (int q = 0; q < 4; q++) c[r][f][q] = 0.f;

  CP_WAIT(0);
  __syncthreads();

  for (int ch = 0; ch < 4; ch++) {
    {
      const int row = t >> 2, quad = t & 3;
      float v[16];
#pragma unroll
      for (int q = 0; q < 4; q++)
        *(float4*)&v[q * 4] =
            *(const float4*)(sm + K1_FX + (uint32_t)(row * 68 + quad * 16 + q * 4) * 4);
      uint4 h0, l0, h1, l1;
      split8(v, h0, l0); split8(v + 8, h1, l1);
      const uint32_t off = (uint32_t)(row * 72 + quad * 16) * 2;
      *(uint4*)(sm + K1_AH + off) = h0; *(uint4*)(sm + K1_AH + off + 16) = h1;
      *(uint4*)(sm + K1_AL + off) = l0; *(uint4*)(sm + K1_AL + off + 16) = l1;
    }
    {
      const int row = t >> 1, half = (t & 1) * 32;
      float v[32];
#pragma unroll
      for (int q = 0; q < 8; q++)
        *(float4*)&v[q * 4] =
            *(const float4*)(sm + K1_FW + (uint32_t)(row * 68 + half + q * 4) * 4);
      const uint32_t off = (uint32_t)(row * 72 + half) * 2;
#pragma unroll
      for (int g = 0; g < 4; g++) {
        uint4 hh, ll;
        split8(v + g * 8, hh, ll);
        *(uint4*)(sm + K1_BH + off + g * 16) = hh;
        *(uint4*)(sm + K1_BL + off + g * 16) = ll;
      }
    }
    __syncthreads();
    if (ch < 3) { K1_LOADF32(ch + 1); CP_COMMIT(); }

#pragma unroll
    for (int ks = 0; ks < 64; ks += 16) {
      const uint32_t lrow = (uint32_t)(lane & 15);
      const uint32_t lcol = (uint32_t)(ks + ((lane >> 4) << 3));
      uint32_t ah[2][4], al[2][4];
#pragma unroll
      for (int r = 0; r < 2; r++) {
        uint32_t ra = SB + ((warpM * 32 + r * 16 + lrow) * 72 + lcol) * 2;
        ldsm4(ra + K1_AH, ah[r]);
        ldsm4(ra + K1_AL, al[r]);
      }
      uint32_t bh[8][2], bl[8][2];
#pragma unroll
      for (int q = 0; q < 4; q++) {
        uint32_t rb = SB + ((warpN * 64 + q * 16 + lrow) * 72 + lcol) * 2;
        uint32_t rr[4];
        ldsm4(rb + K1_BH, rr);
        bh[2 * q][0] = rr[0]; bh[2 * q + 1][0] = rr[1];
        bh[2 * q][1] = rr[2]; bh[2 * q + 1][1] = rr[3];
        ldsm4(rb + K1_BL, rr);
        bl[2 * q][0] = rr[0]; bl[2 * q + 1][0] = rr[1];
        bl[2 * q][1] = rr[2]; bl[2 * q + 1][1] = rr[3];
      }
#pragma unroll
      for (int r = 0; r < 2; r++)
#pragma unroll
        for (int f = 0; f < 8; f++) mma16816(c[r][f], ah[r], bh[f][0], bh[f][1]);
#pragma unroll
      for (int r = 0; r < 2; r++)
#pragma unroll
        for (int f = 0; f < 8; f++) mma16816(c[r][f], ah[r], bl[f][0], bl[f][1]);
#pragma unroll
      for (int r = 0; r < 2; r++)
#pragma unroll
        for (int f = 0; f < 8; f++) mma16816(c[r][f], al[r], bh[f][0], bh[f][1]);
    }
    CP_WAIT(0);
    __syncthreads();
  }

  // ---- epilogue: s1/s2 partials + h fp32 stores ----
  const float* as_ = (const float*)(sm + K1_AS);
  float s1p[4], s2p[4];
#pragma unroll
  for (int q = 0; q < 4; q++) { s1p[q] = 0.f; s2p[q] = 0.f; }
#pragma unroll
  for (int r = 0; r < 2; r++)
#pragma unroll
    for (int f = 0; f < 8; f++)
#pragma unroll
      for (int q = 0; q < 4; q++) {
        int col = warpN * 64 + f * 8 + 2 * (lane & 3) + (q & 1);
        int ri = r * 2 + (q >> 1);
        s1p[ri] += c[r][f][q] * as_[col];
        s2p[ri] += c[r][f][q] * as_[256 + col];
      }
#pragma unroll
  for (int o = 1; o < 4; o <<= 1)
#pragma unroll
    for (int ri = 0; ri < 4; ri++) {
      s1p[ri] += __shfl_xor_sync(0xffffffffu, s1p[ri], o);
      s2p[ri] += __shfl_xor_sync(0xffffffffu, s2p[ri], o);
    }
  if ((lane & 3) == 0) {
#pragma unroll
    for (int r = 0; r < 2; r++)
#pragma unroll
      for (int hh = 0; hh < 2; hh++) {
        int rowr = warpM * 32 + r * 16 + (lane >> 2) + hh * 8;
        ((float*)(sm + K1_R1))[warpN * 128 + rowr] = s1p[r * 2 + hh];
        ((float*)(sm + K1_R2))[warpN * 128 + rowr] = s2p[r * 2 + hh];
      }
  }
#pragma unroll
  for (int r = 0; r < 2; r++)
#pragma unroll
    for (int f = 0; f < 8; f++) {
      int row0 = i0 + warpM * 32 + r * 16 + (lane >> 2);
      int col0 = warpN * 64 + f * 8 + 2 * (lane & 3);
#pragma unroll
      for (int hh = 0; hh < 2; hh++) {
        size_t base = (size_t)(row0 + hh * 8) * 256 + col0;
        *(float2*)&g_hf[base] = make_float2(c[r][f][hh * 2], c[r][f][hh * 2 + 1]);
      }
    }
  __syncthreads();
  if (t < 128) {
    const float* r1 = (const float*)(sm + K1_R1);
    const float* r2 = (const float*)(sm + K1_R2);
    float v1 = 0.f, v2 = 0.f;
#pragma unroll
    for (int wn = 0; wn < 4; wn++) { v1 += r1[wn * 128 + t]; v2 += r2[wn * 128 + t]; }
    g_s1[i0 + t] = v1;
    g_s2[i0 + t] = v2;
  }
}

// ============================================================================
// k_sort: per-batch bitonic sort of s2 (descending) + scalar scans dp/dn.
// ============================================================================
__global__ __launch_bounds__(1024) void k_sort() {
  __shared__ float sv[2048];
  __shared__ int   si[2048];
  __shared__ float sa[2048];
  const int t = threadIdx.x, b = blockIdx.x;

  sv[t] = g_s2[b * 2048 + t];          si[t] = t;
  sv[t + 1024] = g_s2[b * 2048 + t + 1024]; si[t + 1024] = t + 1024;
  __syncthreads();

  for (int kk = 2; kk <= 2048; kk <<= 1)
    for (int jj = kk >> 1; jj > 0; jj >>= 1) {
      int i = ((t & ~(jj - 1)) << 1) | (t & (jj - 1));
      int ixj = i | jj;
      bool desc = ((i & kk) == 0);
      float a = sv[i], c = sv[ixj];
      if (desc ? (a < c) : (a > c)) {
        sv[i] = c; sv[ixj] = a;
        int tmp = si[i]; si[i] = si[ixj]; si[ixj] = tmp;
      }
      __syncthreads();
    }

  g_s2s[b * 2048 + t] = sv[t];
  g_s2s[b * 2048 + t + 1024] = sv[t + 1024];
  g_perm[b * 2048 + t] = si[t];
  g_perm[b * 2048 + t + 1024] = si[t + 1024];

  // ---- scalar prefix of ep = exp(s2_sorted) ----
  sa[t] = __expf(sv[t]);
  sa[t + 1024] = __expf(sv[t + 1024]);
  __syncthreads();
  g_ep[b * 2048 + t] = sa[t];
  g_ep[b * 2048 + t + 1024] = sa[t + 1024];
  for (int off = 1; off < 2048; off <<= 1) {
    float v0 = sa[t] + ((t >= off) ? sa[t - off] : 0.f);
    float v1 = sa[t + 1024] + ((t + 1024 >= off) ? sa[t + 1024 - off] : 0.f);
    __syncthreads();
    sa[t] = v0; sa[t + 1024] = v1;
    __syncthreads();
  }
  if (t == 0) g_dp[b * 2049] = 0.f;
  g_dp[b * 2049 + t + 1] = sa[t];
  g_dp[b * 2049 + t + 1025] = sa[t + 1024];
  __syncthreads();

  // ---- scalar suffix of en = exp(.2*s2_sorted) ----
  sa[t] = __expf(NEG_SLOPE * sv[t]);
  sa[t + 1024] = __expf(NEG_SLOPE * sv[t + 1024]);
  __syncthreads();
  g_en[b * 2048 + t] = sa[t];
  g_en[b * 2048 + t + 1024] = sa[t + 1024];
  for (int off = 1; off < 2048; off <<= 1) {
    float v0 = sa[t] + ((t + off < 2048) ? sa[t + off] : 0.f);
    float v1 = sa[t + 1024] + ((t + 1024 + off < 2048) ? sa[t + 1024 + off] : 0.f);
    __syncthreads();
    sa[t] = v0; sa[t + 1024] = v1;
    __syncthreads();
  }
  g_dn[b * 2049 + t] = sa[t];
  g_dn[b * 2049 + t + 1024] = sa[t + 1024];
  if (t == 0) g_dn[b * 2049 + 2048] = 0.f;
}

// ============================================================================
// k_scanloc: per (batch, 128-rank segment): local vector scans.
//   Pl[k][d] = sum over ranks [seg_start, k) of ep*h   (exclusive prefix)
//   Nl[k][d] = sum over ranks [k, seg_end)   of en*h   (inclusive suffix)
// plus segment totals.
// ============================================================================
__global__ __launch_bounds__(256) void k_scanloc() {
  __shared__ int   sperm[128];
  __shared__ float sep[128], sen[128];
  const int d = threadIdx.x;
  const int s = blockIdx.x, b = blockIdx.y;
  const int k0 = s * 128;

  if (d < 128) {
    sperm[d] = g_perm[b * 2048 + k0 + d];
    sep[d] = g_ep[b * 2048 + k0 + d];
    sen[d] = g_en[b * 2048 + k0 + d];
  }
  __syncthreads();

  float acc = 0.f;
#pragma unroll 4
  for (int r = 0; r < 128; r++) {
    float v = g_hf[((size_t)(b * 2048 + sperm[r])) * 256 + d];
    g_Pl[((size_t)(b * 2049 + k0 + r)) * 256 + d] = acc;
    acc += sep[r] * v;
  }
  g_segP[(b * 16 + s) * 256 + d] = acc;

  acc = 0.f;
#pragma unroll 4
  for (int r = 127; r >= 0; r--) {
    float v = g_hf[((size_t)(b * 2048 + sperm[r])) * 256 + d];
    acc += sen[r] * v;
    g_Nl[((size_t)(b * 2049 + k0 + r)) * 256 + d] = acc;
  }
  g_segN[(b * 16 + s) * 256 + d] = acc;
}

// ============================================================================
// k_segscan: per batch: scan segment totals into offsets; zero boundary row.
// ============================================================================
__global__ __launch_bounds__(256) void k_segscan() {
  const int d = threadIdx.x, b = blockIdx.x;
  float acc = 0.f;
#pragma unroll
  for (int s = 0; s < 16; s++) {
    g_offP[(b * 17 + s) * 256 + d] = acc;
    acc += g_segP[(b * 16 + s) * 256 + d];
  }
  g_offP[(b * 17 + 16) * 256 + d] = acc;
  acc = 0.f;
#pragma unroll
  for (int s = 15; s >= 0; s--) {
    g_offN[(b * 17 + s) * 256 + d] = acc;
    acc += g_segN[(b * 16 + s) * 256 + d];
  }
  g_offN[(b * 17 + 16) * 256 + d] = 0.f;
  g_Pl[((size_t)(b * 2049 + 2048)) * 256 + d] = 0.f;
  g_Nl[((size_t)(b * 2049 + 2048)) * 256 + d] = 0.f;
}

// ============================================================================
// k_out: per (batch, 128-row tile): binary search k_i, combine, ELU, store.
// ============================================================================
#define KO_SV 0                 // 2048 f32
#define KO_DP 8192              // 2049 f32
#define KO_DN 16388             // 2049 f32
#define KO_OP 24584             // 17*256 f32
#define KO_ON 41992             // 17*256 f32
#define KO_KK 59400             // 128 i32
#define KO_CU 59912             // 128 f32
#define KO_CN 60424             // 128 f32
#define KO_SMEM 61440

__global__ __launch_bounds__(256) void k_out(float* __restrict__ out) {
  extern __shared__ char sm[];
  const int t = threadIdx.x;
  const int it = blockIdx.x, b = blockIdx.y;
  const int i0 = it * 128;

  float* sv = (float*)(sm + KO_SV);
  float* sdp = (float*)(sm + KO_DP);
  float* sdn = (float*)(sm + KO_DN);
  float* sop = (float*)(sm + KO_OP);
  float* son = (float*)(sm + KO_ON);
  int* skk = (int*)(sm + KO_KK);
  float* scu = (float*)(sm + KO_CU);
  float* scn = (float*)(sm + KO_CN);

  for (int j = t; j < 2048; j += 256) sv[j] = g_s2s[b * 2048 + j];
  for (int j = t; j < 2049; j += 256) {
    sdp[j] = g_dp[b * 2049 + j];
    sdn[j] = g_dn[b * 2049 + j];
  }
  for (int j = t; j < 17 * 256; j += 256) {
    sop[j] = g_offP[b * 17 * 256 + j];
    son[j] = g_offN[b * 17 * 256 + j];
  }
  __syncthreads();

  if (t < 128) {
    float s1v = g_s1[b * 2048 + i0 + t];
    float tau = -s1v;
    int lo = 0, hi = 2048;
    while (lo < hi) {
      int mid = (lo + hi) >> 1;
      if (sv[mid] > tau) lo = mid + 1; else hi = mid;
    }
    float up = __expf(s1v);
    float un = __expf(NEG_SLOPE * s1v);
    float den = up * sdp[lo] + un * sdn[lo];
    float inv = 1.0f / den;
    skk[t] = lo;
    scu[t] = inv * up;
    scn[t] = inv * un;
  }
  __syncthreads();

  float* ob = out + ((size_t)(b * 2048 + i0)) * 256;
  for (int r = 0; r < 128; r++) {
    int k = skk[r];
    int s = k >> 7;
    float p = g_Pl[((size_t)(b * 2049 + k)) * 256 + t] + sop[s * 256 + t];
    float nn = g_Nl[((size_t)(b * 2049 + k)) * 256 + t] + son[s * 256 + t];
    float v = scu[r] * p + scn[r] * nn;
    v = (v > 0.f) ? v : expm1f(v);
    ob[(size_t)r * 256 + t] = v;
  }
}

// ============================================================================
extern "C" void kernel_launch(void* const* d_in, const int* in_sizes, int n_in,
                              void* d_out, int out_size) {
  (void)in_sizes; (void)n_in; (void)out_size;
  const float* x = (const float*)d_in[0];
  const float* W = (const float*)d_in[1];
  const float* a = (const float*)d_in[2];
  float* out = (float*)d_out;

  cudaFuncSetAttribute(k1, cudaFuncAttributeMaxDynamicSharedMemorySize, K1_SMEM);
  cudaFuncSetAttribute(k_out, cudaFuncAttributeMaxDynamicSharedMemorySize, KO_SMEM);

  k1<<<128, 512, K1_SMEM>>>(x, W, a);
  k_sort<<<B_, 1024>>>();
  k_scanloc<<<dim3(16, B_), 256>>>();
  k_segscan<<<B_, 256>>>();
  k_out<<<dim3(16, B_), 256, KO_SMEM>>>(out);
}

// round 11
// speedup vs baseline: 1.4375x; 1.4375x over previous
#include <cuda_runtime.h>
#include <cuda_fp16.h>
#include <cstdint>

// GraphAttentionLayer B=8,T=2048,D=256 — separable-softmax O(T*D) pipeline.
// w(i,j)=exp(lrelu(s1_i+s2_j)) separates; positive set is a prefix of j
// sorted by s2 desc. Attention = prefix/suffix scans + per-row binary search.
//  k1:       h = x@W^T (split-3 fp16 mma), s1/s2, h fp32
//  k_rank:   rank-by-counting sort of s2 (desc), scatter perm/s2s/ep/en
//  k_scan1:  per-batch scalar prefix dp(ep) / suffix dn(en)
//  k_coef:   per-row binary search k_i + normalization coefficients
//  k_scanloc:per-128-segment vector scans of ep*h (prefix) / en*h (suffix)
//  k_segscan:segment-total offsets (independent loads, register scan)
//  k_out:    one block per row: gather P/N, combine, ELU

#define B_ 8
#define T_ 2048
#define NEG_SLOPE 0.2f

__device__ float g_hf[B_ * T_ * 256];
__device__ float g_s1[B_ * T_];
__device__ float g_s2[B_ * T_];
__device__ float g_s2s[B_ * T_];
__device__ int   g_perm[B_ * T_];
__device__ float g_ep[B_ * T_];
__device__ float g_en[B_ * T_];
__device__ float g_dp[B_ * 2049];
__device__ float g_dn[B_ * 2049];
__device__ int   g_kk[B_ * T_];
__device__ float g_cu[B_ * T_];
__device__ float g_cn[B_ * T_];
__device__ float g_Pl[B_ * 2049 * 256];
__device__ float g_Nl[B_ * 2049 * 256];
__device__ float g_segP[B_ * 16 * 256];
__device__ float g_segN[B_ * 16 * 256];
__device__ float g_offP[B_ * 17 * 256];
__device__ float g_offN[B_ * 17 * 256];

// ---------------- helpers ----------------------------------------------------
__device__ __forceinline__ uint32_t smem_u32(const void* p) {
  uint32_t a;
  asm("{ .reg .u64 t; cvta.to.shared.u64 t, %1; cvt.u32.u64 %0, t; }"
      : "=r"(a) : "l"(p));
  return a;
}
__device__ __forceinline__ void ldsm4(uint32_t addr, uint32_t r[4]) {
  asm volatile("ldmatrix.sync.aligned.m8n8.x4.shared.b16 {%0,%1,%2,%3}, [%4];"
               : "=r"(r[0]), "=r"(r[1]), "=r"(r[2]), "=r"(r[3]) : "r"(addr));
}
__device__ __forceinline__ void mma16816(float c[4], const uint32_t a[4],
                                         uint32_t b0, uint32_t b1) {
  asm volatile(
      "mma.sync.aligned.m16n8k16.row.col.f32.f16.f16.f32 "
      "{%0,%1,%2,%3}, {%4,%5,%6,%7}, {%8,%9}, {%0,%1,%2,%3};"
      : "+f"(c[0]), "+f"(c[1]), "+f"(c[2]), "+f"(c[3])
      : "r"(a[0]), "r"(a[1]), "r"(a[2]), "r"(a[3]), "r"(b0), "r"(b1));
}
__device__ __forceinline__ void cpa16(uint32_t dst, const void* src) {
  asm volatile("cp.async.cg.shared.global [%0], [%1], 16;" :: "r"(dst), "l"(src)
               : "memory");
}
#define CP_COMMIT() asm volatile("cp.async.commit_group;" ::: "memory")
#define CP_WAIT(n) asm volatile("cp.async.wait_group %0;" :: "n"(n) : "memory")

__device__ __forceinline__ void split8(const float* v, uint4& hi, uint4& lo) {
  uint32_t h[4], l[4];
#pragma unroll
  for (int q = 0; q < 4; q++) {
    float a = v[2 * q], b = v[2 * q + 1];
    __half ah = __float2half_rn(a), bh = __float2half_rn(b);
    __half2 hv; hv.x = ah; hv.y = bh; h[q] = *(uint32_t*)&hv;
    __half2 lv;
    lv.x = __float2half_rn(a - __half2float(ah));
    lv.y = __float2half_rn(b - __half2float(bh));
    l[q] = *(uint32_t*)&lv;
  }
  hi = make_uint4(h[0], h[1], h[2], h[3]);
  lo = make_uint4(l[0], l[1], l[2], l[3]);
}

// ============================================================================
// K1: h = x @ W^T (split-3 fp16 mma), epilogue: s1/s2 + h fp32 store.
// ============================================================================
#define K1_FX 0
#define K1_FW 34816
#define K1_AH 104448
#define K1_AL 122880
#define K1_BH 141312
#define K1_BL 178176
#define K1_AS 215040
#define K1_R1 217088
#define K1_R2 219136
#define K1_SMEM 221184

__global__ __launch_bounds__(512, 1) void k1(
    const float* __restrict__ x, const float* __restrict__ W,
    const float* __restrict__ a) {
  extern __shared__ char sm[];
  const uint32_t SB = smem_u32(sm);
  const int t = threadIdx.x, lane = t & 31, wid = t >> 5;
  const int warpM = wid >> 2, warpN = wid & 3;
  const int i0 = blockIdx.x * 128;

#define K1_LOADF32(cc) do {                                                   \
    const int k0_ = (cc) * 64;                                                \
    _Pragma("unroll")                                                         \
    for (int v = 0; v < 4; v++) {                                             \
      int u = v * 512 + t, row = u >> 4, seg = u & 15;                        \
      cpa16(SB + K1_FX + (uint32_t)(row * 68 + seg * 4) * 4,                  \
            &x[(size_t)(i0 + row) * 256 + k0_ + seg * 4]);                    \
    }                                                                         \
    _Pragma("unroll")                                                         \
    for (int v = 0; v < 8; v++) {                                             \
      int u = v * 512 + t, row = u >> 4, seg = u & 15;                        \
      cpa16(SB + K1_FW + (uint32_t)(row * 68 + seg * 4) * 4,                  \
            &W[(size_t)row * 256 + k0_ + seg * 4]);                           \
    }                                                                         \
  } while (0)

  K1_LOADF32(0);
  CP_COMMIT();
  ((float*)(sm + K1_AS))[t] = a[t];

  float c[2][8][4];
#pragma unroll
  for (int r = 0; r < 2; r++)
#pragma unroll
    for (int f = 0; f < 8; f++)
#pragma unroll
      for (int q = 0; q < 4; q++) c[r][f][q] = 0.f;

  CP_WAIT(0);
  __syncthreads();

  for (int ch = 0; ch < 4; ch++) {
    {
      const int row = t >> 2, quad = t & 3;
      float v[16];
#pragma unroll
      for (int q = 0; q < 4; q++)
        *(float4*)&v[q * 4] =
            *(const float4*)(sm + K1_FX + (uint32_t)(row * 68 + quad * 16 + q * 4) * 4);
      uint4 h0, l0, h1, l1;
      split8(v, h0, l0); split8(v + 8, h1, l1);
      const uint32_t off = (uint32_t)(row * 72 + quad * 16) * 2;
      *(uint4*)(sm + K1_AH + off) = h0; *(uint4*)(sm + K1_AH + off + 16) = h1;
      *(uint4*)(sm + K1_AL + off) = l0; *(uint4*)(sm + K1_AL + off + 16) = l1;
    }
    {
      const int row = t >> 1, half = (t & 1) * 32;
      float v[32];
#pragma unroll
      for (int q = 0; q < 8; q++)
        *(float4*)&v[q * 4] =
            *(const float4*)(sm + K1_FW + (uint32_t)(row * 68 + half + q * 4) * 4);
      const uint32_t off = (uint32_t)(row * 72 + half) * 2;
#pragma unroll
      for (int g = 0; g < 4; g++) {
        uint4 hh, ll;
        split8(v + g * 8, hh, ll);
        *(uint4*)(sm + K1_BH + off + g * 16) = hh;
        *(uint4*)(sm + K1_BL + off + g * 16) = ll;
      }
    }
    __syncthreads();
    if (ch < 3) { K1_LOADF32(ch + 1); CP_COMMIT(); }

#pragma unroll
    for (int ks = 0; ks < 64; ks += 16) {
      const uint32_t lrow = (uint32_t)(lane & 15);
      const uint32_t lcol = (uint32_t)(ks + ((lane >> 4) << 3));
      uint32_t ah[2][4], al[2][4];
#pragma unroll
      for (int r = 0; r < 2; r++) {
        uint32_t ra = SB + ((warpM * 32 + r * 16 + lrow) * 72 + lcol) * 2;
        ldsm4(ra + K1_AH, ah[r]);
        ldsm4(ra + K1_AL, al[r]);
      }
      uint32_t bh[8][2], bl[8][2];
#pragma unroll
      for (int q = 0; q < 4; q++) {
        uint32_t rb = SB + ((warpN * 64 + q * 16 + lrow) * 72 + lcol) * 2;
        uint32_t rr[4];
        ldsm4(rb + K1_BH, rr);
        bh[2 * q][0] = rr[0]; bh[2 * q + 1][0] = rr[1];
        bh[2 * q][1] = rr[2]; bh[2 * q + 1][1] = rr[3];
        ldsm4(rb + K1_BL, rr);
        bl[2 * q][0] = rr[0]; bl[2 * q + 1][0] = rr[1];
        bl[2 * q][1] = rr[2]; bl[2 * q + 1][1] = rr[3];
      }
#pragma unroll
      for (int r = 0; r < 2; r++)
#pragma unroll
        for (int f = 0; f < 8; f++) mma16816(c[r][f], ah[r], bh[f][0], bh[f][1]);
#pragma unroll
      for (int r = 0; r < 2; r++)
#pragma unroll
        for (int f = 0; f < 8; f++) mma16816(c[r][f], ah[r], bl[f][0], bl[f][1]);
#pragma unroll
      for (int r = 0; r < 2; r++)
#pragma unroll
        for (int f = 0; f < 8; f++) mma16816(c[r][f], al[r], bh[f][0], bh[f][1]);
    }
    CP_WAIT(0);
    __syncthreads();
  }

  const float* as_ = (const float*)(sm + K1_AS);
  float s1p[4], s2p[4];
#pragma unroll
  for (int q = 0; q < 4; q++) { s1p[q] = 0.f; s2p[q] = 0.f; }
#pragma unroll
  for (int r = 0; r < 2; r++)
#pragma unroll
    for (int f = 0; f < 8; f++)
#pragma unroll
      for (int q = 0; q < 4; q++) {
        int col = warpN * 64 + f * 8 + 2 * (lane & 3) + (q & 1);
        int ri = r * 2 + (q >> 1);
        s1p[ri] += c[r][f][q] * as_[col];
        s2p[ri] += c[r][f][q] * as_[256 + col];
      }
#pragma unroll
  for (int o = 1; o < 4; o <<= 1)
#pragma unroll
    for (int ri = 0; ri < 4; ri++) {
      s1p[ri] += __shfl_xor_sync(0xffffffffu, s1p[ri], o);
      s2p[ri] += __shfl_xor_sync(0xffffffffu, s2p[ri], o);
    }
  if ((lane & 3) == 0) {
#pragma unroll
    for (int r = 0; r < 2; r++)
#pragma unroll
      for (int hh = 0; hh < 2; hh++) {
        int rowr = warpM * 32 + r * 16 + (lane >> 2) + hh * 8;
        ((float*)(sm + K1_R1))[warpN * 128 + rowr] = s1p[r * 2 + hh];
        ((float*)(sm + K1_R2))[warpN * 128 + rowr] = s2p[r * 2 + hh];
      }
  }
#pragma unroll
  for (int r = 0; r < 2; r++)
#pragma unroll
    for (int f = 0; f < 8; f++) {
      int row0 = i0 + warpM * 32 + r * 16 + (lane >> 2);
      int col0 = warpN * 64 + f * 8 + 2 * (lane & 3);
#pragma unroll
      for (int hh = 0; hh < 2; hh++) {
        size_t base = (size_t)(row0 + hh * 8) * 256 + col0;
        *(float2*)&g_hf[base] = make_float2(c[r][f][hh * 2], c[r][f][hh * 2 + 1]);
      }
    }
  __syncthreads();
  if (t < 128) {
    const float* r1 = (const float*)(sm + K1_R1);
    const float* r2 = (const float*)(sm + K1_R2);
    float v1 = 0.f, v2 = 0.f;
#pragma unroll
    for (int wn = 0; wn < 4; wn++) { v1 += r1[wn * 128 + t]; v2 += r2[wn * 128 + t]; }
    g_s1[i0 + t] = v1;
    g_s2[i0 + t] = v2;
  }
}

// ============================================================================
// k_rank: rank-by-counting sort (desc, ties by index). grid (8 seg, 8 b).
// ============================================================================
__global__ __launch_bounds__(256) void k_rank() {
  __shared__ float s2sh[2048];
  const int t = threadIdx.x;
  const int seg = blockIdx.x, b = blockIdx.y;
  for (int j = t; j < 2048; j += 256) s2sh[j] = g_s2[b * 2048 + j];
  __syncthreads();
  const int j = seg * 256 + t;
  const float v = s2sh[j];
  int rank = 0;
#pragma unroll 8
  for (int k = 0; k < 2048; k++) {
    float o = s2sh[k];
    rank += (o > v) || (o == v && k < j);
  }
  g_perm[b * 2048 + rank] = j;
  g_s2s[b * 2048 + rank] = v;
  g_ep[b * 2048 + rank] = __expf(v);
  g_en[b * 2048 + rank] = __expf(NEG_SLOPE * v);
}

// ============================================================================
// k_scan1: per-batch scalar prefix dp (exclusive, of ep) and suffix dn (of en).
// ============================================================================
__global__ __launch_bounds__(1024) void k_scan1() {
  __shared__ float sa[2048];
  const int t = threadIdx.x, b = blockIdx.x;

  sa[t] = g_ep[b * 2048 + t];
  sa[t + 1024] = g_ep[b * 2048 + t + 1024];
  __syncthreads();
  for (int off = 1; off < 2048; off <<= 1) {
    float v0 = sa[t] + ((t >= off) ? sa[t - off] : 0.f);
    float v1 = sa[t + 1024] + ((t + 1024 >= off) ? sa[t + 1024 - off] : 0.f);
    __syncthreads();
    sa[t] = v0; sa[t + 1024] = v1;
    __syncthreads();
  }
  if (t == 0) g_dp[b * 2049] = 0.f;
  g_dp[b * 2049 + t + 1] = sa[t];
  g_dp[b * 2049 + t + 1025] = sa[t + 1024];
  __syncthreads();

  sa[t] = g_en[b * 2048 + t];
  sa[t + 1024] = g_en[b * 2048 + t + 1024];
  __syncthreads();
  for (int off = 1; off < 2048; off <<= 1) {
    float v0 = sa[t] + ((t + off < 2048) ? sa[t + off] : 0.f);
    float v1 = sa[t + 1024] + ((t + 1024 + off < 2048) ? sa[t + 1024 + off] : 0.f);
    __syncthreads();
    sa[t] = v0; sa[t + 1024] = v1;
    __syncthreads();
  }
  g_dn[b * 2049 + t] = sa[t];
  g_dn[b * 2049 + t + 1024] = sa[t + 1024];
  if (t == 0) g_dn[b * 2049 + 2048] = 0.f;
}

// ============================================================================
// k_coef: per-row binary search + coefficients. grid (8 seg, 8 b).
// ============================================================================
__global__ __launch_bounds__(256) void k_coef() {
  __shared__ float sv[2048];
  const int t = threadIdx.x;
  const int seg = blockIdx.x, b = blockIdx.y;
  for (int j = t; j < 2048; j += 256) sv[j] = g_s2s[b * 2048 + j];
  __syncthreads();
  const int i = seg * 256 + t;
  const float s1v = g_s1[b * 2048 + i];
  const float tau = -s1v;
  int lo = 0, hi = 2048;
  while (lo < hi) {
    int mid = (lo + hi) >> 1;
    if (sv[mid] > tau) lo = mid + 1; else hi = mid;
  }
  const float up = __expf(s1v);
  const float un = __expf(NEG_SLOPE * s1v);
  const float inv = 1.0f / (up * g_dp[b * 2049 + lo] + un * g_dn[b * 2049 + lo]);
  g_kk[b * 2048 + i] = lo;
  g_cu[b * 2048 + i] = inv * up;
  g_cn[b * 2048 + i] = inv * un;
}

// ============================================================================
// k_scanloc: per (seg, batch): vector scans, chunk-of-8 loads for MLP.
// ============================================================================
__global__ __launch_bounds__(256) void k_scanloc() {
  __shared__ int   sperm[128];
  __shared__ float sep[128], sen[128];
  const int d = threadIdx.x;
  const int s = blockIdx.x, b = blockIdx.y;
  const int k0 = s * 128;

  if (d < 128) {
    sperm[d] = g_perm[b * 2048 + k0 + d];
    sep[d] = g_ep[b * 2048 + k0 + d];
    sen[d] = g_en[b * 2048 + k0 + d];
  }
  __syncthreads();

  float acc = 0.f;
  for (int r0 = 0; r0 < 128; r0 += 8) {
    float vv[8];
#pragma unroll
    for (int q = 0; q < 8; q++)
      vv[q] = g_hf[((size_t)(b * 2048 + sperm[r0 + q])) * 256 + d];
#pragma unroll
    for (int q = 0; q < 8; q++) {
      g_Pl[((size_t)(b * 2049 + k0 + r0 + q)) * 256 + d] = acc;
      acc += sep[r0 + q] * vv[q];
    }
  }
  g_segP[(b * 16 + s) * 256 + d] = acc;

  acc = 0.f;
  for (int r0 = 120; r0 >= 0; r0 -= 8) {
    float vv[8];
#pragma unroll
    for (int q = 0; q < 8; q++)
      vv[q] = g_hf[((size_t)(b * 2048 + sperm[r0 + q])) * 256 + d];
#pragma unroll
    for (int q = 7; q >= 0; q--) {
      acc += sen[r0 + q] * vv[q];
      g_Nl[((size_t)(b * 2049 + k0 + r0 + q)) * 256 + d] = acc;
    }
  }
  g_segN[(b * 16 + s) * 256 + d] = acc;
}

// ============================================================================
// k_segscan: independent loads -> register scan. grid 8, block 256.
// ============================================================================
__global__ __launch_bounds__(256) void k_segscan() {
  const int d = threadIdx.x, b = blockIdx.x;
  float vP[16], vN[16];
#pragma unroll
  for (int s = 0; s < 16; s++) {
    vP[s] = g_segP[(b * 16 + s) * 256 + d];
    vN[s] = g_segN[(b * 16 + s) * 256 + d];
  }
  float acc = 0.f;
#pragma unroll
  for (int s = 0; s < 16; s++) {
    g_offP[(b * 17 + s) * 256 + d] = acc;
    acc += vP[s];
  }
  g_offP[(b * 17 + 16) * 256 + d] = acc;
  acc = 0.f;
#pragma unroll
  for (int s = 15; s >= 0; s--) {
    g_offN[(b * 17 + s) * 256 + d] = acc;
    acc += vN[s];
  }
  g_offN[(b * 17 + 16) * 256 + d] = 0.f;
  g_Pl[((size_t)(b * 2049 + 2048)) * 256 + d] = 0.f;
  g_Nl[((size_t)(b * 2049 + 2048)) * 256 + d] = 0.f;
}

// ============================================================================
// k_out: one block per output row. grid (2048, 8), block 256.
// ============================================================================
__global__ __launch_bounds__(256) void k_out(float* __restrict__ out) {
  const int d = threadIdx.x;
  const int i = blockIdx.x, b = blockIdx.y;
  const int k = g_kk[b * 2048 + i];
  const float cu = g_cu[b * 2048 + i];
  const float cn = g_cn[b * 2048 + i];
  const int s = k >> 7;
  const float p = g_Pl[((size_t)(b * 2049 + k)) * 256 + d] +
                  g_offP[(b * 17 + s) * 256 + d];
  const float nn = g_Nl[((size_t)(b * 2049 + k)) * 256 + d] +
                   g_offN[(b * 17 + s) * 256 + d];
  float v = cu * p + cn * nn;
  v = (v > 0.f) ? v : expm1f(v);
  out[((size_t)(b * 2048 + i)) * 256 + d] = v;
}

// ============================================================================
extern "C" void kernel_launch(void* const* d_in, const int* in_sizes, int n_in,
                              void* d_out, int out_size) {
  (void)in_sizes; (void)n_in; (void)out_size;
  const float* x = (const float*)d_in[0];
  const float* W = (const float*)d_in[1];
  const float* a = (const float*)d_in[2];
  float* out = (float*)d_out;

  cudaFuncSetAttribute(k1, cudaFuncAttributeMaxDynamicSharedMemorySize, K1_SMEM);

  k1<<<128, 512, K1_SMEM>>>(x, W, a);
  k_rank<<<dim3(8, B_), 256>>>();
  k_scan1<<<B_, 1024>>>();
  k_coef<<<dim3(8, B_), 256>>>();
  k_scanloc<<<dim3(16, B_), 256>>>();
  k_segscan<<<B_, 256>>>();
  k_out<<<dim3(2048, B_), 256>>>(out);
}

// round 12
// speedup vs baseline: 1.5000x; 1.0435x over previous
#include <cuda_runtime.h>
#include <cuda_fp16.h>
#include <cstdint>

// GraphAttentionLayer B=8,T=2048,D=256 — separable-softmax O(T*D) pipeline.
//  k1:       h = x@W^T (split-3 fp16 mma), s1/s2, h fp32
//  k_rank:   rank-by-counting sort of s2 (desc), split-count, scatter
//  k_prep:   fused per-batch scans (dp/dn in smem) + per-row binsearch coefs
//  k_scanloc:per-64-segment vector scans of ep*h (prefix) / en*h (suffix)
//  k_segscan:segment-total offsets (independent loads, register scan)
//  k_out:    one block per row: gather P/N, combine, ELU

#define B_ 8
#define T_ 2048
#define NEG_SLOPE 0.2f

__device__ float g_hf[B_ * T_ * 256];
__device__ float g_s1[B_ * T_];
__device__ float g_s2[B_ * T_];
__device__ float g_s2s[B_ * T_];
__device__ int   g_perm[B_ * T_];
__device__ float g_ep[B_ * T_];
__device__ float g_en[B_ * T_];
__device__ int   g_kk[B_ * T_];
__device__ float g_cu[B_ * T_];
__device__ float g_cn[B_ * T_];
__device__ float g_Pl[B_ * 2049 * 256];
__device__ float g_Nl[B_ * 2049 * 256];
__device__ float g_segP[B_ * 32 * 256];
__device__ float g_segN[B_ * 32 * 256];
__device__ float g_offP[B_ * 33 * 256];
__device__ float g_offN[B_ * 33 * 256];

// ---------------- helpers ----------------------------------------------------
__device__ __forceinline__ uint32_t smem_u32(const void* p) {
  uint32_t a;
  asm("{ .reg .u64 t; cvta.to.shared.u64 t, %1; cvt.u32.u64 %0, t; }"
      : "=r"(a) : "l"(p));
  return a;
}
__device__ __forceinline__ void ldsm4(uint32_t addr, uint32_t r[4]) {
  asm volatile("ldmatrix.sync.aligned.m8n8.x4.shared.b16 {%0,%1,%2,%3}, [%4];"
               : "=r"(r[0]), "=r"(r[1]), "=r"(r[2]), "=r"(r[3]) : "r"(addr));
}
__device__ __forceinline__ void mma16816(float c[4], const uint32_t a[4],
                                         uint32_t b0, uint32_t b1) {
  asm volatile(
      "mma.sync.aligned.m16n8k16.row.col.f32.f16.f16.f32 "
      "{%0,%1,%2,%3}, {%4,%5,%6,%7}, {%8,%9}, {%0,%1,%2,%3};"
      : "+f"(c[0]), "+f"(c[1]), "+f"(c[2]), "+f"(c[3])
      : "r"(a[0]), "r"(a[1]), "r"(a[2]), "r"(a[3]), "r"(b0), "r"(b1));
}
__device__ __forceinline__ void cpa16(uint32_t dst, const void* src) {
  asm volatile("cp.async.cg.shared.global [%0], [%1], 16;" :: "r"(dst), "l"(src)
               : "memory");
}
#define CP_COMMIT() asm volatile("cp.async.commit_group;" ::: "memory")
#define CP_WAIT(n) asm volatile("cp.async.wait_group %0;" :: "n"(n) : "memory")

__device__ __forceinline__ void split8(const float* v, uint4& hi, uint4& lo) {
  uint32_t h[4], l[4];
#pragma unroll
  for (int q = 0; q < 4; q++) {
    float a = v[2 * q], b = v[2 * q + 1];
    __half ah = __float2half_rn(a), bh = __float2half_rn(b);
    __half2 hv; hv.x = ah; hv.y = bh; h[q] = *(uint32_t*)&hv;
    __half2 lv;
    lv.x = __float2half_rn(a - __half2float(ah));
    lv.y = __float2half_rn(b - __half2float(bh));
    l[q] = *(uint32_t*)&lv;
  }
  hi = make_uint4(h[0], h[1], h[2], h[3]);
  lo = make_uint4(l[0], l[1], l[2], l[3]);
}

// ============================================================================
// K1: h = x @ W^T (split-3 fp16 mma), epilogue: s1/s2 + h fp32 store.
// ============================================================================
#define K1_FX 0
#define K1_FW 34816
#define K1_AH 104448
#define K1_AL 122880
#define K1_BH 141312
#define K1_BL 178176
#define K1_AS 215040
#define K1_R1 217088
#define K1_R2 219136
#define K1_SMEM 221184

__global__ __launch_bounds__(512, 1) void k1(
    const float* __restrict__ x, const float* __restrict__ W,
    const float* __restrict__ a) {
  extern __shared__ char sm[];
  const uint32_t SB = smem_u32(sm);
  const int t = threadIdx.x, lane = t & 31, wid = t >> 5;
  const int warpM = wid >> 2, warpN = wid & 3;
  const int i0 = blockIdx.x * 128;

#define K1_LOADF32(cc) do {                                                   \
    const int k0_ = (cc) * 64;                                                \
    _Pragma("unroll")                                                         \
    for (int v = 0; v < 4; v++) {                                             \
      int u = v * 512 + t, row = u >> 4, seg = u & 15;                        \
      cpa16(SB + K1_FX + (uint32_t)(row * 68 + seg * 4) * 4,                  \
            &x[(size_t)(i0 + row) * 256 + k0_ + seg * 4]);                    \
    }                                                                         \
    _Pragma("unroll")                                                         \
    for (int v = 0; v < 8; v++) {                                             \
      int u = v * 512 + t, row = u >> 4, seg = u & 15;                        \
      cpa16(SB + K1_FW + (uint32_t)(row * 68 + seg * 4) * 4,                  \
            &W[(size_t)row * 256 + k0_ + seg * 4]);                           \
    }                                                                         \
  } while (0)

  K1_LOADF32(0);
  CP_COMMIT();
  ((float*)(sm + K1_AS))[t] = a[t];

  float c[2][8][4];
#pragma unroll
  for (int r = 0; r < 2; r++)
#pragma unroll
    for (int f = 0; f < 8; f++)
#pragma unroll
      for (int q = 0; q < 4; q++) c[r][f][q] = 0.f;

  CP_WAIT(0);
  __syncthreads();

  for (int ch = 0; ch < 4; ch++) {
    {
      const int row = t >> 2, quad = t & 3;
      float v[16];
#pragma unroll
      for (int q = 0; q < 4; q++)
        *(float4*)&v[q * 4] =
            *(const float4*)(sm + K1_FX + (uint32_t)(row * 68 + quad * 16 + q * 4) * 4);
      uint4 h0, l0, h1, l1;
      split8(v, h0, l0); split8(v + 8, h1, l1);
      const uint32_t off = (uint32_t)(row * 72 + quad * 16) * 2;
      *(uint4*)(sm + K1_AH + off) = h0; *(uint4*)(sm + K1_AH + off + 16) = h1;
      *(uint4*)(sm + K1_AL + off) = l0; *(uint4*)(sm + K1_AL + off + 16) = l1;
    }
    {
      const int row = t >> 1, half = (t & 1) * 32;
      float v[32];
#pragma unroll
      for (int q = 0; q < 8; q++)
        *(float4*)&v[q * 4] =
            *(const float4*)(sm + K1_FW + (uint32_t)(row * 68 + half + q * 4) * 4);
      const uint32_t off = (uint32_t)(row * 72 + half) * 2;
#pragma unroll
      for (int g = 0; g < 4; g++) {
        uint4 hh, ll;
        split8(v + g * 8, hh, ll);
        *(uint4*)(sm + K1_BH + off + g * 16) = hh;
        *(uint4*)(sm + K1_BL + off + g * 16) = ll;
      }
    }
    __syncthreads();
    if (ch < 3) { K1_LOADF32(ch + 1); CP_COMMIT(); }

#pragma unroll
    for (int ks = 0; ks < 64; ks += 16) {
      const uint32_t lrow = (uint32_t)(lane & 15);
      const uint32_t lcol = (uint32_t)(ks + ((lane >> 4) << 3));
      uint32_t ah[2][4], al[2][4];
#pragma unroll
      for (int r = 0; r < 2; r++) {
        uint32_t ra = SB + ((warpM * 32 + r * 16 + lrow) * 72 + lcol) * 2;
        ldsm4(ra + K1_AH, ah[r]);
        ldsm4(ra + K1_AL, al[r]);
      }
      uint32_t bh[8][2], bl[8][2];
#pragma unroll
      for (int q = 0; q < 4; q++) {
        uint32_t rb = SB + ((warpN * 64 + q * 16 + lrow) * 72 + lcol) * 2;
        uint32_t rr[4];
        ldsm4(rb + K1_BH, rr);
        bh[2 * q][0] = rr[0]; bh[2 * q + 1][0] = rr[1];
        bh[2 * q][1] = rr[2]; bh[2 * q + 1][1] = rr[3];
        ldsm4(rb + K1_BL, rr);
        bl[2 * q][0] = rr[0]; bl[2 * q + 1][0] = rr[1];
        bl[2 * q][1] = rr[2]; bl[2 * q + 1][1] = rr[3];
      }
#pragma unroll
      for (int r = 0; r < 2; r++)
#pragma unroll
        for (int f = 0; f < 8; f++) mma16816(c[r][f], ah[r], bh[f][0], bh[f][1]);
#pragma unroll
      for (int r = 0; r < 2; r++)
#pragma unroll
        for (int f = 0; f < 8; f++) mma16816(c[r][f], ah[r], bl[f][0], bl[f][1]);
#pragma unroll
      for (int r = 0; r < 2; r++)
#pragma unroll
        for (int f = 0; f < 8; f++) mma16816(c[r][f], al[r], bh[f][0], bh[f][1]);
    }
    CP_WAIT(0);
    __syncthreads();
  }

  const float* as_ = (const float*)(sm + K1_AS);
  float s1p[4], s2p[4];
#pragma unroll
  for (int q = 0; q < 4; q++) { s1p[q] = 0.f; s2p[q] = 0.f; }
#pragma unroll
  for (int r = 0; r < 2; r++)
#pragma unroll
    for (int f = 0; f < 8; f++)
#pragma unroll
      for (int q = 0; q < 4; q++) {
        int col = warpN * 64 + f * 8 + 2 * (lane & 3) + (q & 1);
        int ri = r * 2 + (q >> 1);
        s1p[ri] += c[r][f][q] * as_[col];
        s2p[ri] += c[r][f][q] * as_[256 + col];
      }
#pragma unroll
  for (int o = 1; o < 4; o <<= 1)
#pragma unroll
    for (int ri = 0; ri < 4; ri++) {
      s1p[ri] += __shfl_xor_sync(0xffffffffu, s1p[ri], o);
      s2p[ri] += __shfl_xor_sync(0xffffffffu, s2p[ri], o);
    }
  if ((lane & 3) == 0) {
#pragma unroll
    for (int r = 0; r < 2; r++)
#pragma unroll
      for (int hh = 0; hh < 2; hh++) {
        int rowr = warpM * 32 + r * 16 + (lane >> 2) + hh * 8;
        ((float*)(sm + K1_R1))[warpN * 128 + rowr] = s1p[r * 2 + hh];
        ((float*)(sm + K1_R2))[warpN * 128 + rowr] = s2p[r * 2 + hh];
      }
  }
#pragma unroll
  for (int r = 0; r < 2; r++)
#pragma unroll
    for (int f = 0; f < 8; f++) {
      int row0 = i0 + warpM * 32 + r * 16 + (lane >> 2);
      int col0 = warpN * 64 + f * 8 + 2 * (lane & 3);
#pragma unroll
      for (int hh = 0; hh < 2; hh++) {
        size_t base = (size_t)(row0 + hh * 8) * 256 + col0;
        *(float2*)&g_hf[base] = make_float2(c[r][f][hh * 2], c[r][f][hh * 2 + 1]);
      }
    }
  __syncthreads();
  if (t < 128) {
    const float* r1 = (const float*)(sm + K1_R1);
    const float* r2 = (const float*)(sm + K1_R2);
    float v1 = 0.f, v2 = 0.f;
#pragma unroll
    for (int wn = 0; wn < 4; wn++) { v1 += r1[wn * 128 + t]; v2 += r2[wn * 128 + t]; }
    g_s1[i0 + t] = v1;
    g_s2[i0 + t] = v2;
  }
}

// ============================================================================
// k_rank: rank-by-counting (desc, ties by index). Split count: 2 threads per
// j, each counts half the range; combine via shfl. grid (8 seg, 8 b), 512 thr.
// ============================================================================
__global__ __launch_bounds__(512) void k_rank() {
  __shared__ float s2sh[2048];
  const int t = threadIdx.x;
  const int seg = blockIdx.x, b = blockIdx.y;
  for (int j = t; j < 2048; j += 512) s2sh[j] = g_s2[b * 2048 + j];
  __syncthreads();
  const int j = seg * 256 + (t >> 1);
  const int half = t & 1;
  const float v = s2sh[j];
  const int k0 = half * 1024;
  int rank = 0;
#pragma unroll 8
  for (int k = k0; k < k0 + 1024; k++) {
    float o = s2sh[k];
    rank += (o > v) || (o == v && k < j);
  }
  rank += __shfl_xor_sync(0xffffffffu, rank, 1);
  if (half == 0) {
    g_perm[b * 2048 + rank] = j;
    g_s2s[b * 2048 + rank] = v;
    g_ep[b * 2048 + rank] = __expf(v);
    g_en[b * 2048 + rank] = __expf(NEG_SLOPE * v);
  }
}

// ============================================================================
// k_prep: fused per-batch scans + coefficients. grid 8, 1024 thr.
// dp/dn live only in smem; binary search + coef write per row.
// ============================================================================
__global__ __launch_bounds__(1024) void k_prep() {
  __shared__ float sv[2048];
  __shared__ float sa[2048];
  __shared__ float sdp[2049];
  __shared__ float sdn[2049];
  const int t = threadIdx.x, b = blockIdx.x;

  sv[t] = g_s2s[b * 2048 + t];
  sv[t + 1024] = g_s2s[b * 2048 + t + 1024];
  sa[t] = g_ep[b * 2048 + t];
  sa[t + 1024] = g_ep[b * 2048 + t + 1024];
  __syncthreads();
  for (int off = 1; off < 2048; off <<= 1) {
    float v0 = sa[t] + ((t >= off) ? sa[t - off] : 0.f);
    float v1 = sa[t + 1024] + ((t + 1024 >= off) ? sa[t + 1024 - off] : 0.f);
    __syncthreads();
    sa[t] = v0; sa[t + 1024] = v1;
    __syncthreads();
  }
  if (t == 0) sdp[0] = 0.f;
  sdp[t + 1] = sa[t];
  sdp[t + 1025] = sa[t + 1024];
  __syncthreads();

  sa[t] = g_en[b * 2048 + t];
  sa[t + 1024] = g_en[b * 2048 + t + 1024];
  __syncthreads();
  for (int off = 1; off < 2048; off <<= 1) {
    float v0 = sa[t] + ((t + off < 2048) ? sa[t + off] : 0.f);
    float v1 = sa[t + 1024] + ((t + 1024 + off < 2048) ? sa[t + 1024 + off] : 0.f);
    __syncthreads();
    sa[t] = v0; sa[t + 1024] = v1;
    __syncthreads();
  }
  sdn[t] = sa[t];
  sdn[t + 1024] = sa[t + 1024];
  if (t == 0) sdn[2048] = 0.f;
  __syncthreads();

  // coefficients: rows t and t+1024
#pragma unroll
  for (int rr = 0; rr < 2; rr++) {
    const int i = t + rr * 1024;
    const float s1v = g_s1[b * 2048 + i];
    const float tau = -s1v;
    int lo = 0, hi = 2048;
    while (lo < hi) {
      int mid = (lo + hi) >> 1;
      if (sv[mid] > tau) lo = mid + 1; else hi = mid;
    }
    const float up = __expf(s1v);
    const float un = __expf(NEG_SLOPE * s1v);
    const float inv = 1.0f / (up * sdp[lo] + un * sdn[lo]);
    g_kk[b * 2048 + i] = lo;
    g_cu[b * 2048 + i] = inv * up;
    g_cn[b * 2048 + i] = inv * un;
  }
}

// ============================================================================
// k_scanloc: per (64-rank segment, batch): vector scans, chunk-of-8 loads.
// grid (32, 8), block 256.
// ============================================================================
__global__ __launch_bounds__(256) void k_scanloc() {
  __shared__ int   sperm[64];
  __shared__ float sep[64], sen[64];
  const int d = threadIdx.x;
  const int s = blockIdx.x, b = blockIdx.y;
  const int k0 = s * 64;

  if (d < 64) {
    sperm[d] = g_perm[b * 2048 + k0 + d];
    sep[d] = g_ep[b * 2048 + k0 + d];
    sen[d] = g_en[b * 2048 + k0 + d];
  }
  __syncthreads();

  float acc = 0.f;
  for (int r0 = 0; r0 < 64; r0 += 8) {
    float vv[8];
#pragma unroll
    for (int q = 0; q < 8; q++)
      vv[q] = g_hf[((size_t)(b * 2048 + sperm[r0 + q])) * 256 + d];
#pragma unroll
    for (int q = 0; q < 8; q++) {
      g_Pl[((size_t)(b * 2049 + k0 + r0 + q)) * 256 + d] = acc;
      acc += sep[r0 + q] * vv[q];
    }
  }
  g_segP[(b * 32 + s) * 256 + d] = acc;

  acc = 0.f;
  for (int r0 = 56; r0 >= 0; r0 -= 8) {
    float vv[8];
#pragma unroll
    for (int q = 0; q < 8; q++)
      vv[q] = g_hf[((size_t)(b * 2048 + sperm[r0 + q])) * 256 + d];
#pragma unroll
    for (int q = 7; q >= 0; q--) {
      acc += sen[r0 + q] * vv[q];
      g_Nl[((size_t)(b * 2049 + k0 + r0 + q)) * 256 + d] = acc;
    }
  }
  g_segN[(b * 32 + s) * 256 + d] = acc;
}

// ============================================================================
// k_segscan: 32 independent loads -> register scan. grid 8, block 256.
// ============================================================================
__global__ __launch_bounds__(256) void k_segscan() {
  const int d = threadIdx.x, b = blockIdx.x;
  float vP[32], vN[32];
#pragma unroll
  for (int s = 0; s < 32; s++) {
    vP[s] = g_segP[(b * 32 + s) * 256 + d];
    vN[s] = g_segN[(b * 32 + s) * 256 + d];
  }
  float acc = 0.f;
#pragma unroll
  for (int s = 0; s < 32; s++) {
    g_offP[(b * 33 + s) * 256 + d] = acc;
    acc += vP[s];
  }
  g_offP[(b * 33 + 32) * 256 + d] = acc;
  acc = 0.f;
#pragma unroll
  for (int s = 31; s >= 0; s--) {
    g_offN[(b * 33 + s) * 256 + d] = acc;
    acc += vN[s];
  }
  g_offN[(b * 33 + 32) * 256 + d] = 0.f;
  g_Pl[((size_t)(b * 2049 + 2048)) * 256 + d] = 0.f;
  g_Nl[((size_t)(b * 2049 + 2048)) * 256 + d] = 0.f;
}

// ============================================================================
// k_out: one block per output row. grid (2048, 8), block 256.
// ============================================================================
__global__ __launch_bounds__(256) void k_out(float* __restrict__ out) {
  const int d = threadIdx.x;
  const int i = blockIdx.x, b = blockIdx.y;
  const int k = g_kk[b * 2048 + i];
  const float cu = g_cu[b * 2048 + i];
  const float cn = g_cn[b * 2048 + i];
  const int s = k >> 6;
  const float p = g_Pl[((size_t)(b * 2049 + k)) * 256 + d] +
                  g_offP[(b * 33 + s) * 256 + d];
  const float nn = g_Nl[((size_t)(b * 2049 + k)) * 256 + d] +
                   g_offN[(b * 33 + s) * 256 + d];
  float v = cu * p + cn * nn;
  v = (v > 0.f) ? v : expm1f(v);
  out[((size_t)(b * 2048 + i)) * 256 + d] = v;
}

// ============================================================================
extern "C" void kernel_launch(void* const* d_in, const int* in_sizes, int n_in,
                              void* d_out, int out_size) {
  (void)in_sizes; (void)n_in; (void)out_size;
  const float* x = (const float*)d_in[0];
  const float* W = (const float*)d_in[1];
  const float* a = (const float*)d_in[2];
  float* out = (float*)d_out;

  cudaFuncSetAttribute(k1, cudaFuncAttributeMaxDynamicSharedMemorySize, K1_SMEM);

  k1<<<128, 512, K1_SMEM>>>(x, W, a);
  k_rank<<<dim3(8, B_), 512>>>();
  k_prep<<<B_, 1024>>>();
  k_scanloc<<<dim3(32, B_), 256>>>();
  k_segscan<<<B_, 256>>>();
  k_out<<<dim3(2048, B_), 256>>>(out);
}